// round 12
// baseline (speedup 1.0000x reference)
#include <cuda_runtime.h>
#include <cuda_bf16.h>

#define NB     32
#define NZ     100
#define STATE  20
#define HIDN   128
#define HH     32
#define WW     32
#define STEPS  64
#define THRESH 0.1f

#define PIX    1024
#define IMG_SZ (STATE*PIX)
#define STATE_SZ (NB*IMG_SZ)
#define SPR    4
#define NSTRIP 128
#define TOTSTRIP 4096

// ---------------- persistent device scratch ----------------
__device__ __align__(16) float g_S[STATE_SZ];
__device__ __align__(16) float g_T[STATE_SZ];
__device__ unsigned char      g_P  [NB*PIX];
__device__ unsigned char      g_HOT[TOTSTRIP];   // strip computed this step
__device__ unsigned char      g_AM [TOTSTRIP];   // per-strip alive-pixel bitmask
// duplicated-pair weights (f32x2-ready):
// w_perc -> [cr=0..59][h][8]: (w0,w0,w1,w1,w2,w2,-,-)
__device__ __align__(16) float g_wpd [60*128*8];
// w_up1 -> [k][h][2]: (w,w)
__device__ __align__(16) float g_wu1d[128*128*2];

// ---------------- f32x2 helpers ----------------
__device__ __forceinline__ unsigned long long pack2(float v) {
    unsigned long long r; asm("mov.b64 %0, {%1, %1};" : "=l"(r) : "f"(v)); return r;
}
__device__ __forceinline__ void fma2(unsigned long long& d,
                                     unsigned long long a, unsigned long long b) {
    asm("fma.rn.f32x2 %0, %1, %2, %0;" : "+l"(d) : "l"(a), "l"(b));
}
__device__ __forceinline__ float2 unpack2(unsigned long long v) {
    float lo, hi; asm("mov.b64 {%0, %1}, %2;" : "=f"(lo), "=f"(hi) : "l"(v));
    return make_float2(lo, hi);
}

// ---------------- weight repack (duplicate into pairs) ----------------
__global__ void k_pack(const float* __restrict__ wp, const float* __restrict__ wu1)
{
    int i = blockIdx.x*256 + threadIdx.x;
    if (i < 128*180) {
        int h = i / 180, k = i % 180;            // k = c*9 + r*3 + kx
        int cr = k / 3, kx = k % 3;
        float v = wp[i];
        g_wpd[(cr*128 + h)*8 + kx*2 + 0] = v;
        g_wpd[(cr*128 + h)*8 + kx*2 + 1] = v;
    }
    if (i < 128*128) {
        int h = i >> 7, k = i & 127;             // wu1[h][k], h = out channel
        float v = wu1[i];
        g_wu1d[(k*128 + h)*2 + 0] = v;
        g_wu1d[(k*128 + h)*2 + 1] = v;
    }
}

// ---------------- zero initial state + flags ----------------
__global__ void k_zero()
{
    int i = blockIdx.x*256 + threadIdx.x;
    if (i < STATE_SZ) g_S[i] = 0.f;
    if (i < TOTSTRIP) g_AM[i] = 0;
}

// ---------------- init MLP: z -> center pixel ----------------
__global__ void k_init(const float* __restrict__ z,
                       const float* __restrict__ w1, const float* __restrict__ b1,
                       const float* __restrict__ w2, const float* __restrict__ b2)
{
    int n = blockIdx.x;
    int t = threadIdx.x;  // 128 threads
    __shared__ float zz[NZ];
    __shared__ float h[50];
    if (t < NZ) zz[t] = z[n*NZ + t];
    __syncthreads();
    if (t < 50) {
        float a = b1[t];
        #pragma unroll 4
        for (int j = 0; j < NZ; j++) a += w1[t*NZ + j] * zz[j];
        h[t] = fmaxf(a, 0.f);
    }
    __syncthreads();
    const int ctr = 16*WW + 16;
    if (t < STATE-1) {
        float a = b2[t];
        #pragma unroll 5
        for (int j = 0; j < 50; j++) a += w2[t*50 + j] * h[j];
        g_S[n*STATE*PIX + (1+t)*PIX + ctr] = a;
    }
    if (t == STATE-1) {
        g_S[n*STATE*PIX + 0*PIX + ctr] = 0.5f;
        g_AM[n*NSTRIP + 16*SPR + 2] = 0x01;   // strip (y=16,sx=2), pixel 0 = col 16
    }
}

// ---------------- step kernel 1: 256 threads, f32x2, pixel-exact gate ----------------
// thread t: h = t&127 (hid channel), ph = t>>7 (pixel half: 0 -> px 0-3, 1 -> px 4-7)
__global__ void __launch_bounds__(256)
k_step1(const float* __restrict__ bp,
        const float* __restrict__ bu1,
        const float* __restrict__ wu2, const float* __restrict__ bu2)
{
    __shared__ __align__(16) float patchA[60*12];   // [c*3+r][col], cols x0-1..x0+8 (+pad)
    __shared__ __align__(16) float patchB[60*12];   // shifted by 1 col
    __shared__ __align__(16) float s_perc[HIDN*8];  // [h][8]
    __shared__ __align__(16) float sh2T[8*132];     // [p][h] (+pad)
    __shared__ int sflag;

    const int sx = blockIdx.x;
    const int x0 = sx * 8;
    const int y  = blockIdx.y;
    const int n  = blockIdx.z;
    const int t  = threadIdx.x;
    const int idx = y*SPR + sx;
    const int se  = n*NSTRIP + idx;

    // ---- hot test: any alive pixel in rows y-2..y+2, cols x0-2..x0+9 ----
    if (t < 32) {
        int h1 = 0;
        if (t < 15) {
            int dy = t/3 - 2, ds = t%3 - 1;
            int yy = y + dy, ss = sx + ds;
            if ((unsigned)yy < (unsigned)HH && (unsigned)ss < (unsigned)SPR) {
                unsigned m = g_AM[n*NSTRIP + yy*SPR + ss];
                unsigned cm = (ds == 0) ? 0xFFu : (ds < 0 ? 0xC0u : 0x03u);
                h1 = (m & cm) != 0;
            }
        }
        h1 = __any_sync(0xffffffffu, h1);
        if (t == 0) {
            sflag = h1;
            g_HOT[se] = (unsigned char)h1;
        }
    }
    __syncthreads();
    if (!sflag) return;

    const float* __restrict__ Sn = g_S + n*IMG_SZ;
    float* __restrict__ Tn = g_T + n*IMG_SZ;

    // ---- load patch [20][3][12] + shifted copy ----
    for (int i = t; i < 60*12; i += 256) {
        int row = i / 12, col = i - row*12;      // row = c*3 + r
        int c = row / 3, r = row - c*3;
        int yy = y - 1 + r, xx = x0 - 1 + col;
        float v = 0.f;
        if (col < 10 && (unsigned)yy < (unsigned)HH && (unsigned)xx < (unsigned)WW)
            v = Sn[c*PIX + yy*WW + xx];
        patchA[i] = v;
        if (col >= 1) patchB[i - 1] = v;
        else          patchB[row*12 + 11] = 0.f;
    }
    __syncthreads();

    // ---- pre-mask for 8 strip pixels ----
    if (t < 8) {
        float m = 0.f;
        #pragma unroll
        for (int r = 0; r < 3; r++)
            #pragma unroll
            for (int cc = 0; cc < 3; cc++)
                m = fmaxf(m, patchA[r*12 + t + cc]);
        g_P[n*PIX + y*WW + x0 + t] = (m > THRESH) ? 1 : 0;
    }

    const int h   = t & 127;
    const int ph  = t >> 7;
    const int pb4 = ph * 4;

    // ---- perceive: 3x3 conv 20->128, 4 px per thread, dup-pair weights ----
    unsigned long long acc0, acc1;
    {
        unsigned long long b2v = pack2(__ldg(&bp[h]));
        acc0 = b2v; acc1 = b2v;
    }
    #pragma unroll 4
    for (int cr = 0; cr < 60; cr++) {
        const ulonglong2 pa = *(const ulonglong2*)&patchA[cr*12 + pb4];      // px (p,p+1)(p+2,p+3)
        const ulonglong2 pb = *(const ulonglong2*)&patchB[cr*12 + pb4];      // px+1 pairs
        const unsigned long long pc = *(const unsigned long long*)&patchA[cr*12 + pb4 + 4]; // (p+4,p+5)
        const ulonglong2 w01 = *(const ulonglong2*)&g_wpd[(cr*128 + h)*8];   // (w0,w0)(w1,w1)
        const unsigned long long w2d = *(const unsigned long long*)&g_wpd[(cr*128 + h)*8 + 4];
        fma2(acc0, w01.x, pa.x); fma2(acc1, w01.x, pa.y);
        fma2(acc0, w01.y, pb.x); fma2(acc1, w01.y, pb.y);
        fma2(acc0, w2d,   pa.y); fma2(acc1, w2d,   pc);
    }
    {
        ulonglong2 st; st.x = acc0; st.y = acc1;
        *(ulonglong2*)&s_perc[h*8 + pb4] = st;
    }
    __syncthreads();

    // ---- up1: 1x1 128->128 + relu, 4 px per thread, dup-pair weights ----
    unsigned long long a1_0, a1_1;
    {
        unsigned long long b2v = pack2(__ldg(&bu1[h]));
        a1_0 = b2v; a1_1 = b2v;
    }
    #pragma unroll 8
    for (int k = 0; k < 128; k++) {
        const unsigned long long W = *(const unsigned long long*)&g_wu1d[(k*128 + h)*2];
        const ulonglong2 v = *(const ulonglong2*)&s_perc[k*8 + pb4];
        fma2(a1_0, W, v.x);
        fma2(a1_1, W, v.y);
    }
    {
        float2 v0 = unpack2(a1_0), v1 = unpack2(a1_1);
        sh2T[(pb4+0)*132 + h] = fmaxf(v0.x, 0.f);
        sh2T[(pb4+1)*132 + h] = fmaxf(v0.y, 0.f);
        sh2T[(pb4+2)*132 + h] = fmaxf(v1.x, 0.f);
        sh2T[(pb4+3)*132 + h] = fmaxf(v1.y, 0.f);
    }
    __syncthreads();

    // ---- up2: 1x1 128->20, T = S + upd (160 outputs over 256 threads) ----
    if (t < 160) {
        int c = t >> 3, p = t & 7;
        unsigned long long A0 = 0ull, A1 = 0ull;
        const ulonglong2* hv = (const ulonglong2*)&sh2T[p*132];
        const ulonglong2* wv = (const ulonglong2*)&wu2[c*128];
        #pragma unroll 8
        for (int k4 = 0; k4 < 32; k4++) {
            const ulonglong2 h2 = hv[k4];
            const ulonglong2 w2 = __ldg(&wv[k4]);
            fma2(A0, w2.x, h2.x);
            fma2(A1, w2.y, h2.y);
        }
        float2 s0 = unpack2(A0), s1 = unpack2(A1);
        float a = __ldg(&bu2[c]) + ((s0.x + s0.y) + (s1.x + s1.y));
        Tn[c*PIX + y*WW + x0 + p] = patchA[(c*3+1)*12 + p + 1] + a;
    }
}

// ---------------- step kernel 2: warp per strip, early-exit, writes alive mask ----------------
__global__ void __launch_bounds__(256)
k_step2()
{
    const int wid  = threadIdx.x >> 5;
    const int lane = threadIdx.x & 31;
    const int e    = blockIdx.x*8 + wid;       // strip id 0..4095
    const int n    = e >> 7;
    const int idx  = e & 127;
    const int y    = idx >> 2;
    const int x0   = (idx & 3) << 3;

    if (!g_HOT[e]) return;     // alive strips are always hot, so cold S==0 already

    const int q   = lane >> 2;       // pixel 0..7
    const int cgp = lane & 3;        // channel group (5 ch each)
    const int x   = x0 + q;
    const int px  = y*WW + x;
    const float* __restrict__ Tn = g_T + n*IMG_SZ;
    float* __restrict__ Sn = g_S + n*IMG_SZ;

    int alive = 0;
    if (cgp == 0) {
        if (g_P[n*PIX + px]) {
            float m = -1.f;
            #pragma unroll
            for (int dy = -1; dy <= 1; dy++) {
                int yy = y + dy;
                if ((unsigned)yy >= (unsigned)HH) continue;
                #pragma unroll
                for (int dx = -1; dx <= 1; dx++) {
                    int xx = x + dx;
                    if ((unsigned)xx >= (unsigned)WW) continue;
                    m = fmaxf(m, Tn[yy*WW + xx]);
                }
            }
            alive = (m > THRESH) ? 1 : 0;
        }
    }
    alive = __shfl_sync(0xffffffffu, alive, lane & ~3);
    unsigned bal = __ballot_sync(0xffffffffu, alive);

    #pragma unroll
    for (int i = 0; i < 5; i++) {
        int c = cgp*5 + i;
        Sn[c*PIX + px] = alive ? Tn[c*PIX + px] : 0.f;
    }
    if (lane == 0) {
        unsigned m = 0;
        #pragma unroll
        for (int qq = 0; qq < 8; qq++)
            m |= ((bal >> (4*qq)) & 1u) << qq;
        g_AM[e] = (unsigned char)m;
    }
}

// ---------------- extract output: ch0 of final state ----------------
__global__ void k_extract(float* __restrict__ out)
{
    int g = blockIdx.x*256 + threadIdx.x;     // 0..32767
    int n = g >> 10, rem = g & 1023;
    out[g] = g_S[n*IMG_SZ + rem];
}

// ---------------- launch ----------------
extern "C" void kernel_launch(void* const* d_in, const int* in_sizes, int n_in,
                              void* d_out, int out_size)
{
    const float* z   = (const float*)d_in[0];
    const float* w1  = (const float*)d_in[1];
    const float* b1  = (const float*)d_in[2];
    const float* w2  = (const float*)d_in[3];
    const float* b2  = (const float*)d_in[4];
    const float* wp  = (const float*)d_in[5];
    const float* bp  = (const float*)d_in[6];
    const float* wu1 = (const float*)d_in[7];
    const float* bu1 = (const float*)d_in[8];
    const float* wu2 = (const float*)d_in[9];
    const float* bu2 = (const float*)d_in[10];
    float* out = (float*)d_out;

    k_pack<<<(128*180 + 255)/256, 256>>>(wp, wu1);
    k_zero<<<(STATE_SZ + 255)/256, 256>>>();
    k_init<<<NB, 128>>>(z, w1, b1, w2, b2);

    for (int s = 0; s < STEPS; s++) {
        k_step1<<<dim3(4, 32, 32), 256>>>(bp, bu1, wu2, bu2);
        k_step2<<<TOTSTRIP/8, 256>>>();
    }
    k_extract<<<(NB*PIX)/256, 256>>>(out);
}

// round 13
// speedup vs baseline: 1.7490x; 1.7490x over previous
#include <cuda_runtime.h>
#include <cuda_bf16.h>

#define NB     32
#define NZ     100
#define STATE  20
#define HIDN   128
#define HH     32
#define WW     32
#define STEPS  64
#define THRESH 0.1f

#define PIX    1024
#define IMG_SZ (STATE*PIX)
#define STATE_SZ (NB*IMG_SZ)
#define SPR    4
#define NSTRIP 128
#define TOTSTRIP 4096

// ---------------- persistent device scratch (ping-pong) ----------------
__device__ __align__(16) float g_T[2*STATE_SZ];
__device__ unsigned char      g_PM[2*TOTSTRIP];   // per-strip pre-mask byte
__device__ unsigned char      g_HT[2*TOTSTRIP];   // per-strip "T computed this step"
// packed weights (R1 layout)
__device__ __align__(16) float g_wp_pad [60*128*4];   // [cr][h][4] (kx 0..2)
__device__ __align__(16) float g_wu1_pad[32*128*4];   // [kg][h][4]

// ---------------- weight repack ----------------
__global__ void k_pack(const float* __restrict__ wp, const float* __restrict__ wu1)
{
    int i = blockIdx.x*256 + threadIdx.x;
    if (i < 128*180) {
        int h = i / 180, k = i % 180;            // k = c*9 + r*3 + kx
        g_wp_pad[(k/3)*512 + h*4 + (k%3)] = wp[i];
    }
    if (i < 128*128) {
        int h = i / 128, k = i % 128;
        g_wu1_pad[(k>>2)*512 + h*4 + (k&3)] = wu1[i];
    }
}

// ---------------- zero T buf0 + all flags (replay determinism) ----------------
__global__ void k_zero()
{
    int i = blockIdx.x*256 + threadIdx.x;
    if (i < STATE_SZ) g_T[i] = 0.f;              // buffer 0 only (buf1 proven unread-before-write)
    if (i < 2*TOTSTRIP) { g_PM[i] = 0; g_HT[i] = 0; }
}

// ---------------- init MLP: z -> center pixel of T buf0 ----------------
__global__ void k_init(const float* __restrict__ z,
                       const float* __restrict__ w1, const float* __restrict__ b1,
                       const float* __restrict__ w2, const float* __restrict__ b2)
{
    int n = blockIdx.x;
    int t = threadIdx.x;  // 128 threads
    __shared__ float zz[NZ];
    __shared__ float h[50];
    if (t < NZ) zz[t] = z[n*NZ + t];
    __syncthreads();
    if (t < 50) {
        float a = b1[t];
        #pragma unroll 4
        for (int j = 0; j < NZ; j++) a += w1[t*NZ + j] * zz[j];
        h[t] = fmaxf(a, 0.f);
    }
    __syncthreads();
    const int ctr = 16*WW + 16;
    if (t < STATE-1) {
        float a = b2[t];
        #pragma unroll 5
        for (int j = 0; j < 50; j++) a += w2[t*50 + j] * h[j];
        g_T[n*IMG_SZ + (1+t)*PIX + ctr] = a;
    }
    if (t == STATE-1) {
        g_T[n*IMG_SZ + ctr] = 0.5f;              // ch0 center
        g_PM[n*NSTRIP + 16*SPR + 2] = 0x01;      // center strip, pixel 0 (=col 16)
        g_HT[n*NSTRIP + 16*SPR + 2] = 1;
    }
}

// ---------------- fused step kernel (R1 core + mask reconstruction) ----------------
// grid: (4, 32, 32) = (strip, row, image); block: 128 threads
__global__ void __launch_bounds__(128)
k_step(int step,
       const float* __restrict__ bp,
       const float* __restrict__ bu1,
       const float* __restrict__ wu2, const float* __restrict__ bu2)
{
    __shared__ __align__(16) float patch[STATE][3][12];
    __shared__ __align__(16) float s_perc[HIDN][8];
    __shared__ __align__(16) float s_h2 [HIDN][8];
    __shared__ __align__(16) float tch0[5][12];   // T_in ch0, rows y-2..y+2, cols x0-2..x0+9
    __shared__ unsigned char s_pm[16], s_hot[16];
    __shared__ unsigned char aflag[3][10];
    __shared__ int sflag;

    const int in = step & 1;
    const float* __restrict__ Tin  = g_T + in*STATE_SZ;
    float*       __restrict__ Tout = g_T + (in^1)*STATE_SZ;
    const unsigned char* __restrict__ PMin  = g_PM + in*TOTSTRIP;
    unsigned char*       __restrict__ PMout = g_PM + (in^1)*TOTSTRIP;
    const unsigned char* __restrict__ HTin  = g_HT + in*TOTSTRIP;
    unsigned char*       __restrict__ HTout = g_HT + (in^1)*TOTSTRIP;

    const int sx = blockIdx.x;
    const int x0 = sx * 8;
    const int y  = blockIdx.y;
    const int n  = blockIdx.z;
    const int t  = threadIdx.x;
    const int se = n*NSTRIP + y*SPR + sx;
    const int first = (step == 0);

    // ---- gate: any pre pixel in rows y-2..y+2, cols x0-2..x0+9 ----
    if (t < 32) {
        int h1 = 0;
        if (t < 15) {
            int dy = t/3 - 2, ds = t%3 - 1;
            int yy = y + dy, ss = sx + ds;
            unsigned pm = 0, ht = 0;
            if ((unsigned)yy < (unsigned)HH && (unsigned)ss < (unsigned)SPR) {
                pm = PMin[n*NSTRIP + yy*SPR + ss];
                ht = HTin[n*NSTRIP + yy*SPR + ss];
            }
            s_pm[t]  = (unsigned char)pm;
            s_hot[t] = (unsigned char)ht;
            unsigned cm = (ds == 0) ? 0xFFu : (ds < 0 ? 0xC0u : 0x03u);
            h1 = (pm & cm) != 0;
        }
        h1 = __any_sync(0xffffffffu, h1);
        if (t == 0) {
            sflag = h1;
            HTout[se] = (unsigned char)h1;
            if (!h1) PMout[se] = 0;    // cold: kill stale parity flags
        }
    }
    __syncthreads();
    if (!sflag) return;

    // ---- stage T_in ch0 5x12, gated by HOT_in of covering strip ----
    if (t < 60) {
        int rr = t / 12, cc = t % 12;
        int yy = y - 2 + rr, xx = x0 - 2 + cc;
        float v = 0.f;
        if ((unsigned)yy < (unsigned)HH && (unsigned)xx < (unsigned)WW) {
            int hidx = rr*3 + ((xx >> 3) - sx + 1);
            if (s_hot[hidx]) v = Tin[n*IMG_SZ + yy*WW + xx];
        }
        tch0[rr][cc] = v;
    }
    __syncthreads();

    // ---- alive flags for 3x10 halo: PMbit ∧ maxpool3(T ch0) > θ ----
    if (t < 30) {
        int r = t / 10, col = t % 10;
        int yy = y - 1 + r, xx = x0 - 1 + col;
        int f = 0;
        if ((unsigned)yy < (unsigned)HH && (unsigned)xx < (unsigned)WW) {
            int pidx = (r + 1)*3 + ((xx >> 3) - sx + 1);
            if ((s_pm[pidx] >> (xx & 7)) & 1) {
                if (first) f = 1;
                else {
                    float m = -1.f;
                    #pragma unroll
                    for (int dr = 0; dr < 3; dr++)
                        #pragma unroll
                        for (int dc = 0; dc < 3; dc++)
                            m = fmaxf(m, tch0[r + dr][col + dc]);
                    f = (m > THRESH) ? 1 : 0;
                }
            }
        }
        aflag[r][col] = (unsigned char)f;
    }
    __syncthreads();

    // ---- build patch = masked S over [20][3][12] ----
    for (int i = t; i < STATE*3*12; i += 128) {
        int c = i / 36, rem = i - c*36, r = rem / 12, col = rem - r*12;
        float v = 0.f;
        if (col < 10 && aflag[r][col]) {
            int yy = y - 1 + r, xx = x0 - 1 + col;
            v = Tin[n*IMG_SZ + c*PIX + yy*WW + xx];
        }
        patch[c][r][col] = v;
    }
    __syncthreads();

    // ---- pre-mask for own 8 pixels -> PM_out byte ----
    if (t < 32) {
        int pre = 0;
        if (t < 8) {
            float m = 0.f;
            #pragma unroll
            for (int r = 0; r < 3; r++)
                #pragma unroll
                for (int cc = 0; cc < 3; cc++)
                    m = fmaxf(m, patch[0][r][t + cc]);
            pre = (m > THRESH) ? 1 : 0;
        }
        unsigned bal = __ballot_sync(0xffffffffu, pre);
        if (t == 0) PMout[se] = (unsigned char)(bal & 0xFF);
    }

    // ---- perceive: 3x3 conv 20->128 (R1 verbatim) ----
    float acc[8];
    {
        float b = bp[t];
        #pragma unroll
        for (int p = 0; p < 8; p++) acc[p] = b;
    }
    #pragma unroll 2
    for (int c = 0; c < STATE; c++) {
        #pragma unroll
        for (int r = 0; r < 3; r++) {
            const float4 a = *(const float4*)&patch[c][r][0];
            const float4 b = *(const float4*)&patch[c][r][4];
            const float4 d = *(const float4*)&patch[c][r][8];
            float rv[12] = {a.x,a.y,a.z,a.w, b.x,b.y,b.z,b.w, d.x,d.y,d.z,d.w};
            const float4 w4 = *(const float4*)&g_wp_pad[(c*3 + r)*512 + t*4];
            float wk[3] = {w4.x, w4.y, w4.z};
            #pragma unroll
            for (int kx = 0; kx < 3; kx++)
                #pragma unroll
                for (int p = 0; p < 8; p++)
                    acc[p] = fmaf(wk[kx], rv[p + kx], acc[p]);
        }
    }
    #pragma unroll
    for (int p = 0; p < 8; p++) s_perc[t][p] = acc[p];
    __syncthreads();

    // ---- up1: 1x1 128->128 + ReLU (R1 verbatim) ----
    float acc2[8];
    {
        float b = bu1[t];
        #pragma unroll
        for (int p = 0; p < 8; p++) acc2[p] = b;
    }
    #pragma unroll 4
    for (int kg = 0; kg < 32; kg++) {
        const float4 w4 = *(const float4*)&g_wu1_pad[kg*512 + t*4];
        float wk[4] = {w4.x, w4.y, w4.z, w4.w};
        #pragma unroll
        for (int j = 0; j < 4; j++) {
            int k = kg*4 + j;
            const float4 va = *(const float4*)&s_perc[k][0];
            const float4 vb = *(const float4*)&s_perc[k][4];
            acc2[0] = fmaf(wk[j], va.x, acc2[0]);
            acc2[1] = fmaf(wk[j], va.y, acc2[1]);
            acc2[2] = fmaf(wk[j], va.z, acc2[2]);
            acc2[3] = fmaf(wk[j], va.w, acc2[3]);
            acc2[4] = fmaf(wk[j], vb.x, acc2[4]);
            acc2[5] = fmaf(wk[j], vb.y, acc2[5]);
            acc2[6] = fmaf(wk[j], vb.z, acc2[6]);
            acc2[7] = fmaf(wk[j], vb.w, acc2[7]);
        }
    }
    #pragma unroll
    for (int p = 0; p < 8; p++) s_h2[t][p] = fmaxf(acc2[p], 0.f);
    __syncthreads();

    // ---- up2: 1x1 128->20, T_out = maskedS + upd (R1 verbatim) ----
    {
        int c = t >> 3, p = t & 7;
        float a = bu2[c];
        #pragma unroll 8
        for (int k4 = 0; k4 < 32; k4++) {
            const float4 w4 = *(const float4*)&wu2[c*128 + k4*4];
            a = fmaf(w4.x, s_h2[k4*4+0][p], a);
            a = fmaf(w4.y, s_h2[k4*4+1][p], a);
            a = fmaf(w4.z, s_h2[k4*4+2][p], a);
            a = fmaf(w4.w, s_h2[k4*4+3][p], a);
        }
        Tout[n*IMG_SZ + c*PIX + y*WW + x0 + p] = patch[c][1][p+1] + a;
    }
    if (t < 32) {
        int i = t + 128;
        int c = i >> 3, p = i & 7;
        float a = bu2[c];
        #pragma unroll 8
        for (int k4 = 0; k4 < 32; k4++) {
            const float4 w4 = *(const float4*)&wu2[c*128 + k4*4];
            a = fmaf(w4.x, s_h2[k4*4+0][p], a);
            a = fmaf(w4.y, s_h2[k4*4+1][p], a);
            a = fmaf(w4.z, s_h2[k4*4+2][p], a);
            a = fmaf(w4.w, s_h2[k4*4+3][p], a);
        }
        Tout[n*IMG_SZ + c*PIX + y*WW + x0 + p] = patch[c][1][p+1] + a;
    }
}

// ---------------- extract: reconstruct masked ch0 from final buffers (parity 0) ----------------
__global__ void k_extract(float* __restrict__ out)
{
    int g = blockIdx.x*256 + threadIdx.x;     // 0..32767
    int n = g >> 10, rem = g & 1023;
    int y = rem >> 5, x = rem & 31;

    float v = 0.f;
    unsigned pm = g_PM[n*NSTRIP + y*SPR + (x >> 3)];
    if ((pm >> (x & 7)) & 1) {
        const float* __restrict__ Tn = g_T + n*IMG_SZ;
        float m = -1.f;
        #pragma unroll
        for (int dy = -1; dy <= 1; dy++) {
            int yy = y + dy;
            if ((unsigned)yy >= (unsigned)HH) continue;
            #pragma unroll
            for (int dx = -1; dx <= 1; dx++) {
                int xx = x + dx;
                if ((unsigned)xx >= (unsigned)WW) continue;
                if (g_HT[n*NSTRIP + yy*SPR + (xx >> 3)])
                    m = fmaxf(m, Tn[yy*WW + xx]);
            }
        }
        if (m > THRESH) v = Tn[rem];
    }
    out[g] = v;
}

// ---------------- launch ----------------
extern "C" void kernel_launch(void* const* d_in, const int* in_sizes, int n_in,
                              void* d_out, int out_size)
{
    const float* z   = (const float*)d_in[0];
    const float* w1  = (const float*)d_in[1];
    const float* b1  = (const float*)d_in[2];
    const float* w2  = (const float*)d_in[3];
    const float* b2  = (const float*)d_in[4];
    const float* wp  = (const float*)d_in[5];
    const float* bp  = (const float*)d_in[6];
    const float* wu1 = (const float*)d_in[7];
    const float* bu1 = (const float*)d_in[8];
    const float* wu2 = (const float*)d_in[9];
    const float* bu2 = (const float*)d_in[10];
    float* out = (float*)d_out;

    k_pack<<<(128*180 + 255)/256, 256>>>(wp, wu1);
    k_zero<<<(STATE_SZ + 255)/256, 256>>>();
    k_init<<<NB, 128>>>(z, w1, b1, w2, b2);

    for (int s = 0; s < STEPS; s++)
        k_step<<<dim3(4, 32, 32), 128>>>(s, bp, bu1, wu2, bu2);

    k_extract<<<(NB*PIX)/256, 256>>>(out);
}